// round 16
// baseline (speedup 1.0000x reference)
#include <cuda_runtime.h>
#include <cstdint>

// Problem dims
#define DM     1792           // D_MODEL
#define BBDIM  256            // BB
#define I_DIM  2048           // inner dim I
#define G_DIM  8192           // 4*I

#define HALF   370            // blocks per role
#define NBF    740            // one wave at 5 blocks/SM x 148 SMs

#define CH2048B 4096u         // TMA chunk bytes per row, K=2048 (half-K)
#define CH1792B 3584u         // TMA chunk bytes per row, K=1792 (half-K)
#define GSTR ((size_t)I_DIM * I_DIM)   // gate-row stride in floats

// Scratch state (allocation-free rule: __device__ globals)
__device__ float g_z[6 * G_DIM];
__device__ float g_h[2][I_DIM];
__device__ float g_c[2][I_DIM];

__device__ __forceinline__ float sigmoidf_(float x) {
    return 1.0f / (1.0f + expf(-x));
}
__device__ __forceinline__ float dot4(float4 a, float4 b) {
    return a.x * b.x + a.y * b.y + a.z * b.z + a.w * b.w;
}
__device__ __forceinline__ float warp_sum(float v) {
#pragma unroll
    for (int o = 16; o > 0; o >>= 1) v += __shfl_xor_sync(0xffffffffu, v, o);
    return v;
}

// ---------------- TMA bulk-copy plumbing ----------------
__device__ __forceinline__ uint32_t smem_u32(const void* p) {
    return (uint32_t)__cvta_generic_to_shared(p);
}
__device__ __forceinline__ void mbar_init(uint32_t m, uint32_t cnt) {
    asm volatile("mbarrier.init.shared.b64 [%0], %1;" :: "r"(m), "r"(cnt) : "memory");
}
__device__ __forceinline__ void fence_async() {
    asm volatile("fence.proxy.async.shared::cta;" ::: "memory");
}
__device__ __forceinline__ void mbar_expect(uint32_t m, uint32_t tx) {
    asm volatile("mbarrier.arrive.expect_tx.shared.b64 _, [%0], %1;"
                 :: "r"(m), "r"(tx) : "memory");
}
__device__ __forceinline__ void bulk_g2s(uint32_t dst, const void* src,
                                         uint32_t bytes, uint32_t mbar) {
    asm volatile(
        "cp.async.bulk.shared::cluster.global.mbarrier::complete_tx::bytes "
        "[%0], [%1], %2, [%3];"
        :: "r"(dst), "l"(src), "r"(bytes), "r"(mbar) : "memory");
}
__device__ __forceinline__ void mbar_wait(uint32_t m, uint32_t parity) {
    asm volatile(
        "{\n\t.reg .pred P;\n"
        "WL_%=:\n\t"
        "mbarrier.try_wait.parity.shared.b64 P, [%0], %1, 0x989680;\n\t"
        "@P bra DONE_%=;\n\t"
        "bra WL_%=;\n"
        "DONE_%=:\n\t}"
        :: "r"(m), "r"(parity) : "memory");
}

// Issue one chunk-stage: 4 rows, rowStrideF floats between rows, chunkB bytes.
__device__ __forceinline__ void issue4(uint32_t dst, const float* base,
                                       size_t rowStrideF, uint32_t chunkB,
                                       uint32_t mb) {
    mbar_expect(mb, 4 * chunkB);
#pragma unroll
    for (int rr = 0; rr < 4; ++rr)
        bulk_g2s(dst + rr * chunkB, base + (size_t)rr * rowStrideF, chunkB, mb);
}

// smem chunk dot: NIT float4 per lane, conflict-free.
template <int NIT>
__device__ __forceinline__ float chunk_dot(const float4* __restrict__ row,
                                           const float4* __restrict__ v,
                                           int lane) {
    float a = 0.f;
#pragma unroll
    for (int i = 0; i < NIT; ++i) a += dot4(row[lane + i * 32], v[lane + i * 32]);
    return a;
}

// LDG row dot: one full row per warp, streaming loads.
template <int NIT>
__device__ __forceinline__ float ldg_row_dot(const float* __restrict__ row,
                                             const float* __restrict__ vsm,
                                             int lane) {
    const float4* r4 = (const float4*)row;
    const float4* v4 = (const float4*)vsm;
    float a0 = 0.f, a1 = 0.f;
#pragma unroll
    for (int i = 0; i < NIT; i += 2) {
        float4 w0 = __ldcs(r4 + lane + i * 32);
        float4 w1 = __ldcs(r4 + lane + (i + 1) * 32);
        a0 += dot4(w0, v4[lane + i * 32]);
        a1 += dot4(w1, v4[lane + (i + 1) * 32]);
    }
    return a0 + a1;
}

__device__ __forceinline__ void rec_epilogue(int j, const float* d,
                                             int zoff, int pin, int pout) {
    const float* z = g_z + zoff;
    float gi = z[j]             + d[0];
    float gf = z[I_DIM + j]     + d[1];
    float gg = z[2 * I_DIM + j] + d[2];
    float go = z[3 * I_DIM + j] + d[3];
    float c  = sigmoidf_(gf) * g_c[pin][j] + sigmoidf_(gi) * tanhf(gg);
    g_c[pout][j] = c;
    g_h[pout][j] = sigmoidf_(go) * tanhf(c);
}

// ---------------------------------------------------------------------------
// K0: z for cells 0,1. Hybrid: pair p = 8 rows; rows 8p..8p+3 via LDG (one
// per warp), rows 8p+4..8p+7 via TMA double-stage. 370 blocks per cell.
// ---------------------------------------------------------------------------
__global__ void __launch_bounds__(128, 5) k0_hyb(
    const float* __restrict__ x, const float* __restrict__ y,
    const float* __restrict__ Wih5,
    const float* __restrict__ bih5, const float* __restrict__ bhh5)
{
    __shared__ float4 stage[2][1024];
    __shared__ float  vsm[I_DIM];
    __shared__ __align__(8) unsigned long long mbar[2];

    const int tid = threadIdx.x, w = tid >> 5, lane = tid & 31;
    const uint32_t mb0 = smem_u32(&mbar[0]), mb1 = smem_u32(&mbar[1]);

    if (tid == 0) { mbar_init(mb0, 1); mbar_init(mb1, 1); fence_async(); }
    __syncthreads();

    const int t  = blockIdx.x / HALF;
    const int n0 = blockIdx.x % HALF;
    const float* W = Wih5 + (size_t)t * G_DIM * I_DIM;
    const int zbase = t * G_DIM;
    const int np = (1024 - n0 + HALF - 1) / HALF;   // pairs: p = n0 + HALF*i

    if (tid == 0) {
        const float* b0 = W + (size_t)(8 * n0 + 4) * I_DIM;
        issue4(smem_u32(stage[0]), b0,        I_DIM, CH2048B, mb0);
        issue4(smem_u32(stage[1]), b0 + 1024, I_DIM, CH2048B, mb1);
    }
    for (int k = tid; k < DM; k += 128)    vsm[k]      = x[t * DM + k];
    for (int k = tid; k < BBDIM; k += 128) vsm[DM + k] = y[t * BBDIM + k];
    __syncthreads();

    for (int i = 0; i < np; ++i) {
        const int p = n0 + HALF * i;
        const float* nb = W + (size_t)(8 * (p + HALF) + 4) * I_DIM;

        // LDG half (rows 8p..8p+3), overlaps in-flight TMA
        float sA = warp_sum(ldg_row_dot<16>(W + (size_t)(8 * p + w) * I_DIM, vsm, lane));
        if (lane == 0) {
            const int zi = zbase + 8 * p + w;
            g_z[zi] = sA + bih5[zi] + bhh5[zi];
        }

        // TMA half (rows 8p+4..8p+7)
        mbar_wait(mb0, i & 1);
        float sB = chunk_dot<8>(stage[0] + w * 256, (const float4*)vsm, lane);
        __syncthreads();
        if (tid == 0 && i + 1 < np) { fence_async(); issue4(smem_u32(stage[0]), nb, I_DIM, CH2048B, mb0); }

        mbar_wait(mb1, i & 1);
        sB += chunk_dot<8>(stage[1] + w * 256, (const float4*)vsm + 256, lane);
        sB = warp_sum(sB);
        if (lane == 0) {
            const int zi = zbase + 8 * p + 4 + w;
            g_z[zi] = sB + bih5[zi] + bhh5[zi];
        }
        __syncthreads();
        if (tid == 0 && i + 1 < np) { fence_async(); issue4(smem_u32(stage[1]), nb + 1024, I_DIM, CH2048B, mb1); }
    }
}

// ---------------------------------------------------------------------------
// step 0: h0 = c0 = 0 -> no Whh read.
// ---------------------------------------------------------------------------
__global__ void step0_kernel() {
    int j = blockIdx.x * blockDim.x + threadIdx.x;
    if (j >= I_DIM) return;
    float zi = g_z[j];
    float zg = g_z[2 * I_DIM + j];
    float zo = g_z[3 * I_DIM + j];
    float c  = sigmoidf_(zi) * tanhf(zg);
    float h  = sigmoidf_(zo) * tanhf(c);
    g_c[0][j] = c;
    g_h[0][j] = h;
}

// ---------------------------------------------------------------------------
// Fused step, 740 blocks, hybrid both roles.
// [0,370): rec — pair p: jA=2p via LDG (warp w = gate w), jB=2p+1 via TMA
//          (4 gate rows of jB, base = whh + jB*I_DIM, row stride = GSTR).
// [370,740): z for next cell — pair = 8 rows: 4 LDG + 4 TMA.
//   mode 0: 1024 pairs of Wih5[t+1], K=2048.
//   mode 1: 128 pairs, final-cell slice of WihF, K=1792.
// ---------------------------------------------------------------------------
__global__ void __launch_bounds__(128, 5) fused_hyb(
    const float* __restrict__ whh, int zoff, int pin, int pout,
    const float* __restrict__ wz,
    const float* __restrict__ xvec, const float* __restrict__ yvec,
    const float* __restrict__ bih,  const float* __restrict__ bhh,
    int zout, int mode)
{
    __shared__ float4 stage[2][1024];
    __shared__ float  vsm[I_DIM];
    __shared__ float  dotsA[4], dotsB[4];
    __shared__ __align__(8) unsigned long long mbar[2];

    const int tid = threadIdx.x, w = tid >> 5, lane = tid & 31;
    const uint32_t mb0 = smem_u32(&mbar[0]), mb1 = smem_u32(&mbar[1]);

    if (tid == 0) { mbar_init(mb0, 1); mbar_init(mb1, 1); fence_async(); }
    __syncthreads();

    if (blockIdx.x < HALF) {
        // ---------------- rec role ----------------
        const int n0 = blockIdx.x;
        const int np = (1024 - n0 + HALF - 1) / HALF;

        if (tid == 0) {
            const float* b0 = whh + (size_t)(2 * n0 + 1) * I_DIM;
            issue4(smem_u32(stage[0]), b0,        GSTR, CH2048B, mb0);
            issue4(smem_u32(stage[1]), b0 + 1024, GSTR, CH2048B, mb1);
        }
        {
            const float4* gh4 = (const float4*)g_h[pin];
            float4* s4 = (float4*)vsm;
#pragma unroll
            for (int k = 0; k < 4; ++k) s4[tid + k * 128] = gh4[tid + k * 128];
        }
        __syncthreads();

        for (int i = 0; i < np; ++i) {
            const int p  = n0 + HALF * i;
            const int jA = 2 * p, jB = 2 * p + 1;
            const float* nb = whh + (size_t)(2 * (p + HALF) + 1) * I_DIM;

            // LDG: gate row w of jA (overlaps in-flight TMA)
            float sA = warp_sum(ldg_row_dot<16>(
                whh + ((size_t)w * I_DIM + jA) * I_DIM, vsm, lane));
            if (lane == 0) dotsA[w] = sA;

            // TMA: 4 gate rows of jB, two half-K stages
            mbar_wait(mb0, i & 1);
            float sB = chunk_dot<8>(stage[0] + w * 256, (const float4*)vsm, lane);
            __syncthreads();
            if (tid == 0 && i + 1 < np) { fence_async(); issue4(smem_u32(stage[0]), nb, GSTR, CH2048B, mb0); }

            mbar_wait(mb1, i & 1);
            sB += chunk_dot<8>(stage[1] + w * 256, (const float4*)vsm + 256, lane);
            sB = warp_sum(sB);
            if (lane == 0) dotsB[w] = sB;
            __syncthreads();

            if (tid == 0) {
                if (i + 1 < np) { fence_async(); issue4(smem_u32(stage[1]), nb + 1024, GSTR, CH2048B, mb1); }
                rec_epilogue(jA, dotsA, zoff, pin, pout);
            } else if (tid == 1) {
                rec_epilogue(jB, dotsB, zoff, pin, pout);
            }
            __syncthreads();       // dots reused next iteration
        }
    } else {
        // ---------------- z role ----------------
        const int n0   = blockIdx.x - HALF;
        const int lim  = (mode == 0) ? 1024 : 128;   // pairs
        const int np   = (n0 < lim) ? (lim - n0 + HALF - 1) / HALF : 0;
        const int K    = (mode == 0) ? I_DIM : DM;
        const int NF   = (mode == 0) ? 16 : 14;      // float4 per lane per row
        const int HF4  = (mode == 0) ? 256 : 224;    // half-K float4 per row
        const uint32_t chB = (mode == 0) ? CH2048B : CH1792B;

        auto pbase = [&](int p) -> int {             // first row of pair p
            if (mode == 0) return p * 8;
            int rl = p * 8;
            return (rl >> 8) * I_DIM + DM + (rl & 255);
        };

        if (tid == 0 && np > 0) {
            const float* b0 = wz + (size_t)(pbase(n0) + 4) * K;
            issue4(smem_u32(stage[0]), b0,          K, chB, mb0);
            issue4(smem_u32(stage[1]), b0 + K / 2,  K, chB, mb1);
        }
        for (int k = tid; k < DM; k += 128) vsm[k] = xvec[k];
        if (mode == 0)
            for (int k = tid; k < BBDIM; k += 128) vsm[DM + k] = yvec[k];
        __syncthreads();

        for (int i = 0; i < np; ++i) {
            const int p  = n0 + HALF * i;
            const int r0 = pbase(p);
            const float* nb = (i + 1 < np)
                ? wz + (size_t)(pbase(p + HALF) + 4) * K : nullptr;

            // LDG: rows r0..r0+3, one per warp
            float sA = (NF == 16)
                ? warp_sum(ldg_row_dot<16>(wz + (size_t)(r0 + w) * K, vsm, lane))
                : warp_sum(ldg_row_dot<14>(wz + (size_t)(r0 + w) * K, vsm, lane));
            if (lane == 0) {
                const int r = r0 + w;
                g_z[zout + r] = sA + bih[r] + bhh[r];
            }

            // TMA: rows r0+4..r0+7
            mbar_wait(mb0, i & 1);
            float sB = (NF == 16)
                ? chunk_dot<8>(stage[0] + w * 256, (const float4*)vsm, lane)
                : chunk_dot<7>((const float4*)((const char*)stage[0] + w * CH1792B),
                               (const float4*)vsm, lane);
            __syncthreads();
            if (tid == 0 && i + 1 < np) { fence_async(); issue4(smem_u32(stage[0]), nb, K, chB, mb0); }

            mbar_wait(mb1, i & 1);
            sB += (NF == 16)
                ? chunk_dot<8>(stage[1] + w * 256, (const float4*)vsm + 256, lane)
                : chunk_dot<7>((const float4*)((const char*)stage[1] + w * CH1792B),
                               (const float4*)vsm + HF4, lane);
            sB = warp_sum(sB);
            if (lane == 0) {
                const int r = r0 + 4 + w;
                g_z[zout + r] = sB + bih[r] + bhh[r];
            }
            __syncthreads();
            if (tid == 0 && i + 1 < np) { fence_async(); issue4(smem_u32(stage[1]), nb + K / 2, K, chB, mb1); }
        }
    }
}

// ---------------------------------------------------------------------------
// Final step: j in [1792,2048). 256 blocks, 1 j each (8.4 MB total).
// ---------------------------------------------------------------------------
__global__ void __launch_bounds__(128) final_pipe(
    const float* __restrict__ whhF, int pin, float* __restrict__ out)
{
    __shared__ float4 stage[2][1024];
    __shared__ float  vsm[I_DIM];
    __shared__ float  dots[4];
    __shared__ __align__(8) unsigned long long mbar[2];

    const int tid = threadIdx.x, w = tid >> 5, lane = tid & 31;
    const uint32_t mb0 = smem_u32(&mbar[0]), mb1 = smem_u32(&mbar[1]);

    if (tid == 0) { mbar_init(mb0, 1); mbar_init(mb1, 1); fence_async(); }
    __syncthreads();

    const int j = DM + blockIdx.x;
    if (tid == 0) {
        const float* b0 = whhF + (size_t)j * I_DIM;
        issue4(smem_u32(stage[0]), b0,        GSTR, CH2048B, mb0);
        issue4(smem_u32(stage[1]), b0 + 1024, GSTR, CH2048B, mb1);
    }
    {
        const float4* gh4 = (const float4*)g_h[pin];
        float4* s4 = (float4*)vsm;
#pragma unroll
        for (int k = 0; k < 4; ++k) s4[tid + k * 128] = gh4[tid + k * 128];
    }
    __syncthreads();

    mbar_wait(mb0, 0);
    float acc = chunk_dot<8>(stage[0] + w * 256, (const float4*)vsm, lane);
    mbar_wait(mb1, 0);
    acc += chunk_dot<8>(stage[1] + w * 256, (const float4*)vsm + 256, lane);
    acc = warp_sum(acc);
    if (lane == 0) dots[w] = acc;
    __syncthreads();

    if (tid == 0) {
        const float* z = g_z + 5 * G_DIM;
        float gi = z[j]             + dots[0];
        float gf = z[I_DIM + j]     + dots[1];
        float gg = z[2 * I_DIM + j] + dots[2];
        float go = z[3 * I_DIM + j] + dots[3];
        float c  = sigmoidf_(gf) * g_c[pin][j] + sigmoidf_(gi) * tanhf(gg);
        float h  = sigmoidf_(go) * tanhf(c);
        out[j - DM] = h;
    }
}

// ---------------------------------------------------------------------------
extern "C" void kernel_launch(void* const* d_in, const int* in_sizes, int n_in,
                              void* d_out, int out_size)
{
    const float* x    = (const float*)d_in[0];
    const float* y    = (const float*)d_in[1];
    const float* Wih5 = (const float*)d_in[2];
    const float* Whh5 = (const float*)d_in[3];
    const float* bih5 = (const float*)d_in[4];
    const float* bhh5 = (const float*)d_in[5];
    const float* WihF = (const float*)d_in[6];
    const float* WhhF = (const float*)d_in[7];
    const float* bihF = (const float*)d_in[8];
    const float* bhhF = (const float*)d_in[9];
    float* out = (float*)d_out;

    (void)in_sizes; (void)n_in; (void)out_size;

    const size_t WSTEP = (size_t)G_DIM * I_DIM;

    // K0: z[0], z[1] (134 MB)
    k0_hyb<<<NBF, 128>>>(x, y, Wih5, bih5, bhh5);

    // step 0 (h0=c0=0: skips Whh5[0], 67 MB)
    step0_kernel<<<(I_DIM + 255) / 256, 256>>>();

    // S1..S3: rec t + z(t+1) (134 MB each)
    int pin = 0;
    for (int t = 1; t <= 3; ++t) {
        fused_hyb<<<NBF, 128>>>(
            Whh5 + (size_t)t * WSTEP, t * G_DIM, pin, 1 - pin,
            Wih5 + (size_t)(t + 1) * WSTEP,
            x + (t + 1) * DM, y + (t + 1) * BBDIM,
            bih5 + (size_t)(t + 1) * G_DIM, bhh5 + (size_t)(t + 1) * G_DIM,
            (t + 1) * G_DIM, /*mode=*/0);
        pin = 1 - pin;
    }

    // S4: rec 4 + final-cell z slice (67 + 7.3 MB)
    fused_hyb<<<NBF, 128>>>(
        Whh5 + (size_t)4 * WSTEP, 4 * G_DIM, pin, 1 - pin,
        WihF, x + 5 * DM, nullptr,
        bihF, bhhF, 5 * G_DIM, /*mode=*/1);
    pin = 1 - pin;

    // S5: final step, 256 outputs (8.4 MB)
    final_pipe<<<256, 128>>>(WhhF, pin, out);
}